// round 15
// baseline (speedup 1.0000x reference)
#include <cuda_runtime.h>
#include <cuda_bf16.h>
#include <math.h>
#include <stdint.h>

#define BB 4
#define TT 2048
#define DM 128
#define NH 4
#define DH 32
#define NROW (BB*TT)

// Scratch (allocation-free rule: __device__ globals)
__device__ __nv_bfloat16 g_Qb[NROW*DM];   // pre-scaled by 1/sqrt(DH)
__device__ __nv_bfloat16 g_Kb[NROW*DM];
__device__ __nv_bfloat16 g_Vb[NROW*DM];
__device__ float g_ctx[NROW*DM];

// ============================ PTX helpers ============================
__device__ __forceinline__ uint32_t smem_u32(const void* p){
    uint32_t a;
    asm("{ .reg .u64 t; cvta.to.shared.u64 t, %1; cvt.u32.u64 %0, t; }" : "=r"(a) : "l"(p));
    return a;
}
__device__ __forceinline__ float ex2f(float x){
    float y; asm("ex2.approx.f32 %0, %1;" : "=f"(y) : "f"(x)); return y;
}
__device__ __forceinline__ void mma16816(float* d, const uint32_t* a, const uint32_t* b){
    asm volatile("mma.sync.aligned.m16n8k16.row.col.f32.bf16.bf16.f32 "
        "{%0,%1,%2,%3}, {%4,%5,%6,%7}, {%8,%9}, {%0,%1,%2,%3};"
        : "+f"(d[0]), "+f"(d[1]), "+f"(d[2]), "+f"(d[3])
        : "r"(a[0]), "r"(a[1]), "r"(a[2]), "r"(a[3]), "r"(b[0]), "r"(b[1]));
}
// init form: c = 0 (RZ) — removes explicit zero-init MOVs; volatile like the rest.
__device__ __forceinline__ void mma16816_init(float* d, const uint32_t* a, const uint32_t* b){
    asm volatile("mma.sync.aligned.m16n8k16.row.col.f32.bf16.bf16.f32 "
        "{%0,%1,%2,%3}, {%4,%5,%6,%7}, {%8,%9}, {%10,%11,%12,%13};"
        : "=f"(d[0]), "=f"(d[1]), "=f"(d[2]), "=f"(d[3])
        : "r"(a[0]), "r"(a[1]), "r"(a[2]), "r"(a[3]), "r"(b[0]), "r"(b[1]),
          "f"(0.0f), "f"(0.0f), "f"(0.0f), "f"(0.0f));
}
__device__ __forceinline__ void ldsm4(uint32_t* r, uint32_t addr){
    asm volatile("ldmatrix.sync.aligned.m8n8.x4.shared.b16 {%0,%1,%2,%3}, [%4];"
        : "=r"(r[0]), "=r"(r[1]), "=r"(r[2]), "=r"(r[3]) : "r"(addr));
}
__device__ __forceinline__ void ldsm4t(uint32_t* r, uint32_t addr){
    asm volatile("ldmatrix.sync.aligned.m8n8.x4.trans.shared.b16 {%0,%1,%2,%3}, [%4];"
        : "=r"(r[0]), "=r"(r[1]), "=r"(r[2]), "=r"(r[3]) : "r"(addr));
}
__device__ __forceinline__ void cpasync16(uint32_t dst, const void* src){
    asm volatile("cp.async.cg.shared.global [%0], [%1], 16;" :: "r"(dst), "l"(src));
}
#define CP_COMMIT()  asm volatile("cp.async.commit_group;" ::: "memory")
#define CP_WAIT1()   asm volatile("cp.async.wait_group 1;"  ::: "memory")
// cvt pack: lower = p0, upper = p1
#define CVT_BF16X2(res, p0, p1) \
    asm("cvt.rn.satfinite.bf16x2.f32 %0, %1, %2;" : "=r"(res) : "f"(p1), "f"(p0))

// SW: chunk c of row r lives at slot (c ^ ((r>>1)&3)); rows are 64B (4x16B chunks)
__device__ __forceinline__ uint32_t sw_off(int row, int chunk){
    return (uint32_t)(row*64 + ((chunk ^ ((row>>1)&3)) << 4));
}

#define TILE_K_BYTES 8192            // 128 keys x 32 bf16
#define TILE_BYTES   16384           // K + V
#define NSTAGE 3

// ---------------------------------------------------------------------------
// Kernel 1: QKV projection -> bf16 (Q pre-scaled by 1/sqrt(DH)).
// R3 version (16 rows/CTA, grid 512, scalar k-loop) — best measured (8.2us).
// ---------------------------------------------------------------------------
__global__ __launch_bounds__(128) void qkv_kernel(
    const float* __restrict__ M,
    const float* __restrict__ Wq, const float* __restrict__ bq,
    const float* __restrict__ Wk, const float* __restrict__ bk,
    const float* __restrict__ Wv, const float* __restrict__ bv)
{
    __shared__ float sx[16][17];
    const int tid = threadIdx.x;
    float wq[16], wk[16], wv[16];
#pragma unroll
    for (int k = 0; k < 16; k++) {
        wq[k] = Wq[k*128 + tid]; wk[k] = Wk[k*128 + tid]; wv[k] = Wv[k*128 + tid];
    }
    const int row0 = blockIdx.x * 16;
    for (int i = tid; i < 256; i += 128) sx[i >> 4][i & 15] = M[(size_t)row0*16 + i];
    __syncthreads();

    const float bqv = bq[tid], bkv = bk[tid], bvv = bv[tid];
    const float qscale = 0.17677669529663687f;   // 1/sqrt(32)
#pragma unroll
    for (int r = 0; r < 16; r++) {
        float aq = bqv, ak = bkv, av = bvv;
#pragma unroll
        for (int k = 0; k < 16; k++) {
            const float xv = sx[r][k];
            aq += xv * wq[k]; ak += xv * wk[k]; av += xv * wv[k];
        }
        const size_t row = row0 + r;
        g_Qb[row*DM + tid] = __float2bfloat16(aq * qscale);
        g_Kb[row*DM + tid] = __float2bfloat16(ak);
        g_Vb[row*DM + tid] = __float2bfloat16(av);
    }
}

// ---------------------------------------------------------------------------
// Kernel 2: FlashAttention-2, mma.sync bf16, cp.async pipeline.
// R13: R12 base ((128,2), fixed-max, init-form QK) + exp/pack fused into the
// PV ks-loop — interleaves MUFU with tensor at 16-key granularity so the two
// warps per SMSP de-phase and overlap pipes. ldsm4t issued before the exps
// to hide its latency under the MUFU batch.
// ---------------------------------------------------------------------------
__global__ __launch_bounds__(128, 2) void attn_kernel()
{
    __shared__ char smem[NSTAGE * TILE_BYTES];
    const uint32_t sbase = smem_u32(smem);

    const int tid = threadIdx.x;
    const int lane = tid & 31;
    const int w = tid >> 5;
    const int b = blockIdx.z, h = blockIdx.y;
    const int q0 = blockIdx.x * 128;

    const int g = lane >> 2, tig = lane & 3;

    // ---- Q A-fragments (held in registers for the whole kernel) ----
    uint32_t qa[2][2][4];
    {
        const __nv_bfloat16* Qb = g_Qb + ((size_t)(b*TT + q0 + w*32 + g))*DM + h*DH;
#pragma unroll
        for (int mt = 0; mt < 2; mt++)
#pragma unroll
            for (int ks = 0; ks < 2; ks++) {
                const uint32_t* p = (const uint32_t*)(Qb + mt*16*DM + ks*16 + 2*tig);
                qa[mt][ks][0] = p[0];
                qa[mt][ks][1] = p[8*(DM/2)];
                qa[mt][ks][2] = p[4];
                qa[mt][ks][3] = p[8*(DM/2) + 4];
            }
    }

    // ---- tile loader (cp.async, 8x16B per thread) ----
    const char* Kg = (const char*)(g_Kb + ((size_t)b*TT)*DM + h*DH);
    const char* Vg = (const char*)(g_Vb + ((size_t)b*TT)*DM + h*DH);
    const int lrow0 = tid >> 2, lc = tid & 3;

#define LOAD_TILE(kt, buf) do { \
    const uint32_t kd = sbase + (buf)*TILE_BYTES; \
    const uint32_t vd = kd + TILE_K_BYTES; \
    const char* ks_ = Kg + (size_t)(kt)*128*(DM*2); \
    const char* vs_ = Vg + (size_t)(kt)*128*(DM*2); \
    _Pragma("unroll") \
    for (int p_ = 0; p_ < 4; p_++) { \
        const int row = lrow0 + p_*32; \
        const uint32_t o = sw_off(row, lc); \
        cpasync16(kd + o, ks_ + (size_t)row*(DM*2) + lc*16); \
        cpasync16(vd + o, vs_ + (size_t)row*(DM*2) + lc*16); \
    } \
} while(0)

    LOAD_TILE(0, 0); CP_COMMIT();
    LOAD_TILE(1, 1); CP_COMMIT();

    // ---- accumulators ----
    float O[2][4][4];
#pragma unroll
    for (int mt = 0; mt < 2; mt++)
#pragma unroll
        for (int dn = 0; dn < 4; dn++)
#pragma unroll
            for (int i = 0; i < 4; i++) O[mt][dn][i] = 0.0f;
    float lrow[4] = {0.0f, 0.0f, 0.0f, 0.0f};
    float ml2[4]  = {0.0f, 0.0f, 0.0f, 0.0f};   // fixed max * log2(e), set at kt==0,s==0

    const int keyLocK = (lane & 7) + ((lane >> 4) & 1) * 8;
    const int chBitK  = (lane >> 3) & 1;
    const int keyLocV = (lane & 7) + ((lane >> 3) & 1) * 8;
    const int chBitV  = (lane >> 4) & 1;
    const float L2E = 1.4426950408889634f;

#pragma unroll 1
    for (int kt = 0; kt < 16; kt++) {
        CP_WAIT1();
        __syncthreads();
        if (kt + 2 < 16) { LOAD_TILE(kt + 2, (kt + 2) % NSTAGE); }
        CP_COMMIT();

        const uint32_t kB = sbase + (kt % NSTAGE) * TILE_BYTES;
        const uint32_t vB = kB + TILE_K_BYTES;

#pragma unroll
        for (int s = 0; s < 2; s++) {
            // ---------------- QK^T -> S [2 mtiles][8 ntiles][4] ----------------
            float S[2][8][4];
#pragma unroll
            for (int pair = 0; pair < 4; pair++) {
                const int key = s*64 + pair*16 + keyLocK;
                uint32_t bf0[4], bf1[4];
                ldsm4(bf0, kB + sw_off(key, chBitK));
                ldsm4(bf1, kB + sw_off(key, 2 + chBitK));
                mma16816_init(S[0][2*pair],   qa[0][0], &bf0[0]);
                mma16816_init(S[0][2*pair+1], qa[0][0], &bf0[2]);
                mma16816_init(S[1][2*pair],   qa[1][0], &bf0[0]);
                mma16816_init(S[1][2*pair+1], qa[1][0], &bf0[2]);
                mma16816(S[0][2*pair],   qa[0][1], &bf1[0]);
                mma16816(S[0][2*pair+1], qa[0][1], &bf1[2]);
                mma16816(S[1][2*pair],   qa[1][1], &bf1[0]);
                mma16816(S[1][2*pair+1], qa[1][1], &bf1[2]);
            }

            // ------- fixed max from the very first sub-block only -------
            if (kt == 0 && s == 0) {
                float bm[4] = {-1e30f, -1e30f, -1e30f, -1e30f};
#pragma unroll
                for (int n = 0; n < 8; n++) {
                    bm[0] = fmaxf(bm[0], fmaxf(S[0][n][0], S[0][n][1]));
                    bm[1] = fmaxf(bm[1], fmaxf(S[0][n][2], S[0][n][3]));
                    bm[2] = fmaxf(bm[2], fmaxf(S[1][n][0], S[1][n][1]));
                    bm[3] = fmaxf(bm[3], fmaxf(S[1][n][2], S[1][n][3]));
                }
#pragma unroll
                for (int i = 0; i < 4; i++) {
                    bm[i] = fmaxf(bm[i], __shfl_xor_sync(0xffffffffu, bm[i], 1));
                    bm[i] = fmaxf(bm[i], __shfl_xor_sync(0xffffffffu, bm[i], 2));
                    ml2[i] = bm[i] * L2E;
                }
            }

            // ------- fused exp + pack + PV per 16-key slice (no rescale) -------
            float ls[4] = {0.0f, 0.0f, 0.0f, 0.0f};
#pragma unroll
            for (int ks = 0; ks < 4; ks++) {
                const int key = s*64 + ks*16 + keyLocV;
                uint32_t bfa[4], bfb[4];
                ldsm4t(bfa, vB + sw_off(key, chBitV));        // dp=0 chunk
                ldsm4t(bfb, vB + sw_off(key, 2 + chBitV));    // dp=1 chunk

                uint32_t P0[4], P1[4];
                {
                    const float a0 = ex2f(fmaf(S[0][2*ks][0],   L2E, -ml2[0]));
                    const float a1 = ex2f(fmaf(S[0][2*ks][1],   L2E, -ml2[0]));
                    const float a2 = ex2f(fmaf(S[0][2*ks][2],   L2E, -ml2[1]));
                    const float a3 = ex2f(fmaf(S[0][2*ks][3],   L2E, -ml2[1]));
                    const float a4 = ex2f(fmaf(S[0][2*ks+1][0], L2E, -ml2[0]));
                    const float a5 = ex2f(fmaf(S[0][2*ks+1][1], L2E, -ml2[0]));
                    const float a6 = ex2f(fmaf(S[0][2*ks+1][2], L2E, -ml2[1]));
                    const float a7 = ex2f(fmaf(S[0][2*ks+1][3], L2E, -ml2[1]));
                    ls[0] += (a0 + a1) + (a4 + a5);
                    ls[1] += (a2 + a3) + (a6 + a7);
                    CVT_BF16X2(P0[0], a0, a1); CVT_BF16X2(P0[1], a2, a3);
                    CVT_BF16X2(P0[2], a4, a5); CVT_BF16X2(P0[3], a6, a7);
                }
                {
                    const float a0 = ex2f(fmaf(S[1][2*ks][0],   L2E, -ml2[2]));
                    const float a1 = ex2f(fmaf(S[1][2*ks][1],   L2E, -ml2[2]));
                    const float a2 = ex2f(fmaf(S[1][2*ks][2],   L2E, -ml2[3]));
                    const float a3 = ex2f(fmaf(S[1][2*ks][3],   L2E, -ml2[3]));
                    const float a4 = ex2f(fmaf(S[1][2*ks+1][0], L2E, -ml2[2]));
                    const float a5 = ex2f(fmaf(S[1][2*ks+1][1], L2E, -ml2[2]));
                    const float a6 = ex2f(fmaf(S[1][2*ks+1][2], L2E, -ml2[3]));
                    const float a7 = ex2f(fmaf(S[1][2*ks+1][3], L2E, -ml2[3]));
                    ls[2] += (a0 + a1) + (a4 + a5);
                    ls[3] += (a2 + a3) + (a6 + a7);
                    CVT_BF16X2(P1[0], a0, a1); CVT_BF16X2(P1[1], a2, a3);
                    CVT_BF16X2(P1[2], a4, a5); CVT_BF16X2(P1[3], a6, a7);
                }
                mma16816(O[0][0], P0, &bfa[0]);
                mma16816(O[0][1], P0, &bfa[2]);
                mma16816(O[1][0], P1, &bfa[0]);
                mma16816(O[1][1], P1, &bfa[2]);
                mma16816(O[0][2], P0, &bfb[0]);
                mma16816(O[0][3], P0, &bfb[2]);
                mma16816(O[1][2], P1, &bfb[0]);
                mma16816(O[1][3], P1, &bfb[2]);
            }
#pragma unroll
            for (int i = 0; i < 4; i++) lrow[i] += ls[i];
        }
    }

    // ---- finalize: reduce l across the 4 lanes of each row group ----
    float inv[4];
#pragma unroll
    for (int i = 0; i < 4; i++) {
        float l = lrow[i];
        l += __shfl_xor_sync(0xffffffffu, l, 1);
        l += __shfl_xor_sync(0xffffffffu, l, 2);
        inv[i] = 1.0f / l;
    }
    float* Ob = g_ctx + ((size_t)(b*TT + q0 + w*32 + g))*DM + h*DH;
#pragma unroll
    for (int mt = 0; mt < 2; mt++)
#pragma unroll
        for (int dn = 0; dn < 4; dn++) {
            float* p0 = Ob + mt*16*DM + dn*8 + 2*tig;
            *(float2*)p0 = make_float2(O[mt][dn][0]*inv[mt*2+0], O[mt][dn][1]*inv[mt*2+0]);
            *(float2*)(p0 + 8*DM) = make_float2(O[mt][dn][2]*inv[mt*2+1], O[mt][dn][3]*inv[mt*2+1]);
        }
}

// ---------------------------------------------------------------------------
// Kernel 3: epilogue (R11 version).  All global loads LDG.128; transposed-W
// LDS.128 matmul body.
// ---------------------------------------------------------------------------
__global__ __launch_bounds__(256) void epi_kernel(
    const float* __restrict__ M,
    const float* __restrict__ Wo, const float* __restrict__ bo,
    const float* __restrict__ Wg, const float* __restrict__ bg,
    const float* __restrict__ Wb, const float* __restrict__ bb,
    const float* __restrict__ gamma, const float* __restrict__ beta,
    const float* __restrict__ sens, float* __restrict__ out)
{
    __shared__ float sW[3][16][132];   // [which][j][k], pad 132 kills read conflicts
    __shared__ float sctx[16][132];
    __shared__ float ssens[16], sgam[16], sbet[16];
    const int t = threadIdx.x;
    const int row0 = blockIdx.x * 16;

    // weights: 512 float4 per matrix, 2 per thread
#pragma unroll
    for (int p = 0; p < 2; p++) {
        const int i4 = t + p*256;
        const int i = i4 * 4;
        const int k = i >> 4, j = i & 15;          // j, j+1, j+2, j+3 share k
        const float4 vo = ((const float4*)Wo)[i4];
        const float4 vg = ((const float4*)Wg)[i4];
        const float4 vb = ((const float4*)Wb)[i4];
        sW[0][j+0][k] = vo.x; sW[0][j+1][k] = vo.y; sW[0][j+2][k] = vo.z; sW[0][j+3][k] = vo.w;
        sW[1][j+0][k] = vg.x; sW[1][j+1][k] = vg.y; sW[1][j+2][k] = vg.z; sW[1][j+3][k] = vg.w;
        sW[2][j+0][k] = vb.x; sW[2][j+1][k] = vb.y; sW[2][j+2][k] = vb.z; sW[2][j+3][k] = vb.w;
    }
    // ctx: 512 float4, 2 per thread; sctx rows are 132 floats = 528B (16B aligned)
    const float4* ctx4 = (const float4*)(g_ctx + (size_t)row0*DM);
#pragma unroll
    for (int p = 0; p < 2; p++) {
        const int i4 = t + p*256;
        const int i = i4 * 4;
        *(float4*)&sctx[i >> 7][i & 127] = ctx4[i4];
    }
    if (t < 16) { ssens[t] = sens[t]; sgam[t] = gamma[t]; sbet[t] = beta[t]; }
    __syncthreads();

    const int r = t >> 4, j = t & 15;
    const float4* c4  = (const float4*)&sctx[r][0];
    const float4* wo4 = (const float4*)&sW[0][j][0];
    const float4* wg4 = (const float4*)&sW[1][j][0];
    const float4* wb4 = (const float4*)&sW[2][j][0];
    float dacc = bo[j], gacc = bg[j], bacc = bb[j];
#pragma unroll
    for (int k4 = 0; k4 < 32; k4++) {
        const float4 cv = c4[k4];
        const float4 a = wo4[k4], bgv = wg4[k4], bbv = wb4[k4];
        dacc += cv.x*a.x   + cv.y*a.y   + cv.z*a.z   + cv.w*a.w;
        gacc += cv.x*bgv.x + cv.y*bgv.y + cv.z*bgv.z + cv.w*bgv.w;
        bacc += cv.x*bbv.x + cv.y*bbv.y + cv.z*bbv.z + cv.w*bbv.w;
    }
    const float mval = M[(size_t)(row0 + r)*16 + j];
    const float G  = (1.0f / (1.0f + __expf(-gacc))) * ssens[j];
    const float Bt = tanhf(bacc);
    const float mu = mval * (1.0f - G) + dacc * G + 0.1f * Bt;

    float sum = mu;
#pragma unroll
    for (int off = 8; off; off >>= 1) sum += __shfl_xor_sync(0xffffffffu, sum, off, 16);
    const float mean = sum * 0.0625f;
    const float d = mu - mean;
    float v = d * d;
#pragma unroll
    for (int off = 8; off; off >>= 1) v += __shfl_xor_sync(0xffffffffu, v, off, 16);
    const float var = v * 0.0625f;
    out[(size_t)(row0 + r)*16 + j] = d * rsqrtf(var + 1e-6f) * sgam[j] + sbet[j];
}

// ---------------------------------------------------------------------------
extern "C" void kernel_launch(void* const* d_in, const int* in_sizes, int n_in,
                              void* d_out, int out_size)
{
    const float* M  = (const float*)d_in[0];
    const float* Wq = (const float*)d_in[1];  const float* bq = (const float*)d_in[2];
    const float* Wk = (const float*)d_in[3];  const float* bk = (const float*)d_in[4];
    const float* Wv = (const float*)d_in[5];  const float* bv = (const float*)d_in[6];
    const float* Wo = (const float*)d_in[7];  const float* bo = (const float*)d_in[8];
    const float* Wg = (const float*)d_in[9];  const float* bg = (const float*)d_in[10];
    const float* Wb = (const float*)d_in[11]; const float* bb = (const float*)d_in[12];
    const float* gamma = (const float*)d_in[13];
    const float* beta  = (const float*)d_in[14];
    const float* sens  = (const float*)d_in[15];
    float* out = (float*)d_out;

    qkv_kernel<<<NROW/16, 128>>>(M, Wq, bq, Wk, bk, Wv, bv);
    attn_kernel<<<dim3(TT/128, NH, BB), 128>>>();
    epi_kernel<<<NROW/16, 256>>>(M, Wo, bo, Wg, bg, Wb, bb, gamma, beta, sens, out);
}

// round 16
// speedup vs baseline: 1.0187x; 1.0187x over previous
#include <cuda_runtime.h>
#include <cuda_bf16.h>
#include <math.h>
#include <stdint.h>

#define BB 4
#define TT 2048
#define DM 128
#define NH 4
#define DH 32
#define NROW (BB*TT)

// Scratch (allocation-free rule: __device__ globals)
__device__ __nv_bfloat16 g_Qb[NROW*DM];   // pre-scaled by 1/sqrt(DH)
__device__ __nv_bfloat16 g_Kb[NROW*DM];
__device__ __nv_bfloat16 g_Vb[NROW*DM];
__device__ float g_ctx[NROW*DM];

// ============================ PTX helpers ============================
__device__ __forceinline__ uint32_t smem_u32(const void* p){
    uint32_t a;
    asm("{ .reg .u64 t; cvta.to.shared.u64 t, %1; cvt.u32.u64 %0, t; }" : "=r"(a) : "l"(p));
    return a;
}
__device__ __forceinline__ float ex2f(float x){
    float y; asm("ex2.approx.f32 %0, %1;" : "=f"(y) : "f"(x)); return y;
}
__device__ __forceinline__ void mma16816(float* d, const uint32_t* a, const uint32_t* b){
    asm volatile("mma.sync.aligned.m16n8k16.row.col.f32.bf16.bf16.f32 "
        "{%0,%1,%2,%3}, {%4,%5,%6,%7}, {%8,%9}, {%0,%1,%2,%3};"
        : "+f"(d[0]), "+f"(d[1]), "+f"(d[2]), "+f"(d[3])
        : "r"(a[0]), "r"(a[1]), "r"(a[2]), "r"(a[3]), "r"(b[0]), "r"(b[1]));
}
// init form: c = 0 (RZ) — removes explicit zero-init MOVs; volatile like the rest.
__device__ __forceinline__ void mma16816_init(float* d, const uint32_t* a, const uint32_t* b){
    asm volatile("mma.sync.aligned.m16n8k16.row.col.f32.bf16.bf16.f32 "
        "{%0,%1,%2,%3}, {%4,%5,%6,%7}, {%8,%9}, {%10,%11,%12,%13};"
        : "=f"(d[0]), "=f"(d[1]), "=f"(d[2]), "=f"(d[3])
        : "r"(a[0]), "r"(a[1]), "r"(a[2]), "r"(a[3]), "r"(b[0]), "r"(b[1]),
          "f"(0.0f), "f"(0.0f), "f"(0.0f), "f"(0.0f));
}
__device__ __forceinline__ void ldsm4(uint32_t* r, uint32_t addr){
    asm volatile("ldmatrix.sync.aligned.m8n8.x4.shared.b16 {%0,%1,%2,%3}, [%4];"
        : "=r"(r[0]), "=r"(r[1]), "=r"(r[2]), "=r"(r[3]) : "r"(addr));
}
__device__ __forceinline__ void ldsm4t(uint32_t* r, uint32_t addr){
    asm volatile("ldmatrix.sync.aligned.m8n8.x4.trans.shared.b16 {%0,%1,%2,%3}, [%4];"
        : "=r"(r[0]), "=r"(r[1]), "=r"(r[2]), "=r"(r[3]) : "r"(addr));
}
__device__ __forceinline__ void cpasync16(uint32_t dst, const void* src){
    asm volatile("cp.async.cg.shared.global [%0], [%1], 16;" :: "r"(dst), "l"(src));
}
#define CP_COMMIT()  asm volatile("cp.async.commit_group;" ::: "memory")
#define CP_WAIT1()   asm volatile("cp.async.wait_group 1;"  ::: "memory")
// cvt pack: lower = p0, upper = p1
#define CVT_BF16X2(res, p0, p1) \
    asm("cvt.rn.satfinite.bf16x2.f32 %0, %1, %2;" : "=r"(res) : "f"(p1), "f"(p0))

// SW: chunk c of row r lives at slot (c ^ ((r>>1)&3)); rows are 64B (4x16B chunks)
__device__ __forceinline__ uint32_t sw_off(int row, int chunk){
    return (uint32_t)(row*64 + ((chunk ^ ((row>>1)&3)) << 4));
}

#define TILE_K_BYTES 8192            // 128 keys x 32 bf16
#define TILE_BYTES   16384           // K + V
#define NSTAGE 3

// ---------------------------------------------------------------------------
// Kernel 1: QKV projection -> bf16 (Q pre-scaled by 1/sqrt(DH)).
// R3 version (16 rows/CTA, grid 512, scalar k-loop) — best measured (8.2us).
// ---------------------------------------------------------------------------
__global__ __launch_bounds__(128) void qkv_kernel(
    const float* __restrict__ M,
    const float* __restrict__ Wq, const float* __restrict__ bq,
    const float* __restrict__ Wk, const float* __restrict__ bk,
    const float* __restrict__ Wv, const float* __restrict__ bv)
{
    __shared__ float sx[16][17];
    const int tid = threadIdx.x;
    float wq[16], wk[16], wv[16];
#pragma unroll
    for (int k = 0; k < 16; k++) {
        wq[k] = Wq[k*128 + tid]; wk[k] = Wk[k*128 + tid]; wv[k] = Wv[k*128 + tid];
    }
    const int row0 = blockIdx.x * 16;
    for (int i = tid; i < 256; i += 128) sx[i >> 4][i & 15] = M[(size_t)row0*16 + i];
    __syncthreads();

    const float bqv = bq[tid], bkv = bk[tid], bvv = bv[tid];
    const float qscale = 0.17677669529663687f;   // 1/sqrt(32)
#pragma unroll
    for (int r = 0; r < 16; r++) {
        float aq = bqv, ak = bkv, av = bvv;
#pragma unroll
        for (int k = 0; k < 16; k++) {
            const float xv = sx[r][k];
            aq += xv * wq[k]; ak += xv * wk[k]; av += xv * wv[k];
        }
        const size_t row = row0 + r;
        g_Qb[row*DM + tid] = __float2bfloat16(aq * qscale);
        g_Kb[row*DM + tid] = __float2bfloat16(ak);
        g_Vb[row*DM + tid] = __float2bfloat16(av);
    }
}

// ---------------------------------------------------------------------------
// Kernel 2: FlashAttention-2, mma.sync bf16, cp.async pipeline.
// R8/R12 version: (128,2), fixed-max softmax, init-form first QK mma.
// ---------------------------------------------------------------------------
__global__ __launch_bounds__(128, 2) void attn_kernel()
{
    __shared__ char smem[NSTAGE * TILE_BYTES];
    const uint32_t sbase = smem_u32(smem);

    const int tid = threadIdx.x;
    const int lane = tid & 31;
    const int w = tid >> 5;
    const int b = blockIdx.z, h = blockIdx.y;
    const int q0 = blockIdx.x * 128;

    const int g = lane >> 2, tig = lane & 3;

    // ---- Q A-fragments (held in registers for the whole kernel) ----
    uint32_t qa[2][2][4];
    {
        const __nv_bfloat16* Qb = g_Qb + ((size_t)(b*TT + q0 + w*32 + g))*DM + h*DH;
#pragma unroll
        for (int mt = 0; mt < 2; mt++)
#pragma unroll
            for (int ks = 0; ks < 2; ks++) {
                const uint32_t* p = (const uint32_t*)(Qb + mt*16*DM + ks*16 + 2*tig);
                qa[mt][ks][0] = p[0];
                qa[mt][ks][1] = p[8*(DM/2)];
                qa[mt][ks][2] = p[4];
                qa[mt][ks][3] = p[8*(DM/2) + 4];
            }
    }

    // ---- tile loader (cp.async, 8x16B per thread) ----
    const char* Kg = (const char*)(g_Kb + ((size_t)b*TT)*DM + h*DH);
    const char* Vg = (const char*)(g_Vb + ((size_t)b*TT)*DM + h*DH);
    const int lrow0 = tid >> 2, lc = tid & 3;

#define LOAD_TILE(kt, buf) do { \
    const uint32_t kd = sbase + (buf)*TILE_BYTES; \
    const uint32_t vd = kd + TILE_K_BYTES; \
    const char* ks_ = Kg + (size_t)(kt)*128*(DM*2); \
    const char* vs_ = Vg + (size_t)(kt)*128*(DM*2); \
    _Pragma("unroll") \
    for (int p_ = 0; p_ < 4; p_++) { \
        const int row = lrow0 + p_*32; \
        const uint32_t o = sw_off(row, lc); \
        cpasync16(kd + o, ks_ + (size_t)row*(DM*2) + lc*16); \
        cpasync16(vd + o, vs_ + (size_t)row*(DM*2) + lc*16); \
    } \
} while(0)

    LOAD_TILE(0, 0); CP_COMMIT();
    LOAD_TILE(1, 1); CP_COMMIT();

    // ---- accumulators ----
    float O[2][4][4];
#pragma unroll
    for (int mt = 0; mt < 2; mt++)
#pragma unroll
        for (int dn = 0; dn < 4; dn++)
#pragma unroll
            for (int i = 0; i < 4; i++) O[mt][dn][i] = 0.0f;
    float lrow[4] = {0.0f, 0.0f, 0.0f, 0.0f};
    float ml2[4]  = {0.0f, 0.0f, 0.0f, 0.0f};   // fixed max * log2(e), set at kt==0,s==0

    const int keyLocK = (lane & 7) + ((lane >> 4) & 1) * 8;
    const int chBitK  = (lane >> 3) & 1;
    const int keyLocV = (lane & 7) + ((lane >> 3) & 1) * 8;
    const int chBitV  = (lane >> 4) & 1;
    const float L2E = 1.4426950408889634f;

#pragma unroll 1
    for (int kt = 0; kt < 16; kt++) {
        CP_WAIT1();
        __syncthreads();
        if (kt + 2 < 16) { LOAD_TILE(kt + 2, (kt + 2) % NSTAGE); }
        CP_COMMIT();

        const uint32_t kB = sbase + (kt % NSTAGE) * TILE_BYTES;
        const uint32_t vB = kB + TILE_K_BYTES;

#pragma unroll
        for (int s = 0; s < 2; s++) {
            // ---------------- QK^T -> S [2 mtiles][8 ntiles][4] ----------------
            float S[2][8][4];
#pragma unroll
            for (int pair = 0; pair < 4; pair++) {
                const int key = s*64 + pair*16 + keyLocK;
                uint32_t bf0[4], bf1[4];
                ldsm4(bf0, kB + sw_off(key, chBitK));
                ldsm4(bf1, kB + sw_off(key, 2 + chBitK));
                mma16816_init(S[0][2*pair],   qa[0][0], &bf0[0]);
                mma16816_init(S[0][2*pair+1], qa[0][0], &bf0[2]);
                mma16816_init(S[1][2*pair],   qa[1][0], &bf0[0]);
                mma16816_init(S[1][2*pair+1], qa[1][0], &bf0[2]);
                mma16816(S[0][2*pair],   qa[0][1], &bf1[0]);
                mma16816(S[0][2*pair+1], qa[0][1], &bf1[2]);
                mma16816(S[1][2*pair],   qa[1][1], &bf1[0]);
                mma16816(S[1][2*pair+1], qa[1][1], &bf1[2]);
            }

            // ------- fixed max from the very first sub-block only -------
            if (kt == 0 && s == 0) {
                float bm[4] = {-1e30f, -1e30f, -1e30f, -1e30f};
#pragma unroll
                for (int n = 0; n < 8; n++) {
                    bm[0] = fmaxf(bm[0], fmaxf(S[0][n][0], S[0][n][1]));
                    bm[1] = fmaxf(bm[1], fmaxf(S[0][n][2], S[0][n][3]));
                    bm[2] = fmaxf(bm[2], fmaxf(S[1][n][0], S[1][n][1]));
                    bm[3] = fmaxf(bm[3], fmaxf(S[1][n][2], S[1][n][3]));
                }
#pragma unroll
                for (int i = 0; i < 4; i++) {
                    bm[i] = fmaxf(bm[i], __shfl_xor_sync(0xffffffffu, bm[i], 1));
                    bm[i] = fmaxf(bm[i], __shfl_xor_sync(0xffffffffu, bm[i], 2));
                    ml2[i] = bm[i] * L2E;
                }
            }

            // ---------------- exp + pack P + row-sum ----------------
            uint32_t P[2][4][4];
            float ls[4] = {0.0f, 0.0f, 0.0f, 0.0f};
#pragma unroll
            for (int mt = 0; mt < 2; mt++)
#pragma unroll
                for (int n = 0; n < 8; n++) {
                    const float p0 = ex2f(fmaf(S[mt][n][0], L2E, -ml2[mt*2+0]));
                    const float p1 = ex2f(fmaf(S[mt][n][1], L2E, -ml2[mt*2+0]));
                    const float p2 = ex2f(fmaf(S[mt][n][2], L2E, -ml2[mt*2+1]));
                    const float p3 = ex2f(fmaf(S[mt][n][3], L2E, -ml2[mt*2+1]));
                    ls[mt*2+0] += p0 + p1;
                    ls[mt*2+1] += p2 + p3;
                    const int ks = n >> 1, hi = (n & 1) * 2;
                    CVT_BF16X2(P[mt][ks][hi+0], p0, p1);
                    CVT_BF16X2(P[mt][ks][hi+1], p2, p3);
                }
#pragma unroll
            for (int i = 0; i < 4; i++) lrow[i] += ls[i];

            // ---------------- P @ V -> O (no rescale: m is fixed) ----------------
#pragma unroll
            for (int ks = 0; ks < 4; ks++)
#pragma unroll
                for (int dp = 0; dp < 2; dp++) {
                    const int key = s*64 + ks*16 + keyLocV;
                    const int ch  = 2*dp + chBitV;
                    uint32_t bf[4];
                    ldsm4t(bf, vB + sw_off(key, ch));
                    mma16816(O[0][2*dp],   P[0][ks], &bf[0]);
                    mma16816(O[0][2*dp+1], P[0][ks], &bf[2]);
                    mma16816(O[1][2*dp],   P[1][ks], &bf[0]);
                    mma16816(O[1][2*dp+1], P[1][ks], &bf[2]);
                }
        }
    }

    // ---- finalize: reduce l across the 4 lanes of each row group ----
    float inv[4];
#pragma unroll
    for (int i = 0; i < 4; i++) {
        float l = lrow[i];
        l += __shfl_xor_sync(0xffffffffu, l, 1);
        l += __shfl_xor_sync(0xffffffffu, l, 2);
        inv[i] = 1.0f / l;
    }
    float* Ob = g_ctx + ((size_t)(b*TT + q0 + w*32 + g))*DM + h*DH;
#pragma unroll
    for (int mt = 0; mt < 2; mt++)
#pragma unroll
        for (int dn = 0; dn < 4; dn++) {
            float* p0 = Ob + mt*16*DM + dn*8 + 2*tig;
            *(float2*)p0 = make_float2(O[mt][dn][0]*inv[mt*2+0], O[mt][dn][1]*inv[mt*2+0]);
            *(float2*)(p0 + 8*DM) = make_float2(O[mt][dn][2]*inv[mt*2+1], O[mt][dn][3]*inv[mt*2+1]);
        }
}

// ---------------------------------------------------------------------------
// Kernel 3: epilogue (R11 version).  All global loads LDG.128; transposed-W
// LDS.128 matmul body.
// ---------------------------------------------------------------------------
__global__ __launch_bounds__(256) void epi_kernel(
    const float* __restrict__ M,
    const float* __restrict__ Wo, const float* __restrict__ bo,
    const float* __restrict__ Wg, const float* __restrict__ bg,
    const float* __restrict__ Wb, const float* __restrict__ bb,
    const float* __restrict__ gamma, const float* __restrict__ beta,
    const float* __restrict__ sens, float* __restrict__ out)
{
    __shared__ float sW[3][16][132];   // [which][j][k], pad 132 kills read conflicts
    __shared__ float sctx[16][132];
    __shared__ float ssens[16], sgam[16], sbet[16];
    const int t = threadIdx.x;
    const int row0 = blockIdx.x * 16;

    // weights: 512 float4 per matrix, 2 per thread
#pragma unroll
    for (int p = 0; p < 2; p++) {
        const int i4 = t + p*256;
        const int i = i4 * 4;
        const int k = i >> 4, j = i & 15;          // j, j+1, j+2, j+3 share k
        const float4 vo = ((const float4*)Wo)[i4];
        const float4 vg = ((const float4*)Wg)[i4];
        const float4 vb = ((const float4*)Wb)[i4];
        sW[0][j+0][k] = vo.x; sW[0][j+1][k] = vo.y; sW[0][j+2][k] = vo.z; sW[0][j+3][k] = vo.w;
        sW[1][j+0][k] = vg.x; sW[1][j+1][k] = vg.y; sW[1][j+2][k] = vg.z; sW[1][j+3][k] = vg.w;
        sW[2][j+0][k] = vb.x; sW[2][j+1][k] = vb.y; sW[2][j+2][k] = vb.z; sW[2][j+3][k] = vb.w;
    }
    // ctx: 512 float4, 2 per thread; sctx rows are 132 floats = 528B (16B aligned)
    const float4* ctx4 = (const float4*)(g_ctx + (size_t)row0*DM);
#pragma unroll
    for (int p = 0; p < 2; p++) {
        const int i4 = t + p*256;
        const int i = i4 * 4;
        *(float4*)&sctx[i >> 7][i & 127] = ctx4[i4];
    }
    if (t < 16) { ssens[t] = sens[t]; sgam[t] = gamma[t]; sbet[t] = beta[t]; }
    __syncthreads();

    const int r = t >> 4, j = t & 15;
    const float4* c4  = (const float4*)&sctx[r][0];
    const float4* wo4 = (const float4*)&sW[0][j][0];
    const float4* wg4 = (const float4*)&sW[1][j][0];
    const float4* wb4 = (const float4*)&sW[2][j][0];
    float dacc = bo[j], gacc = bg[j], bacc = bb[j];
#pragma unroll
    for (int k4 = 0; k4 < 32; k4++) {
        const float4 cv = c4[k4];
        const float4 a = wo4[k4], bgv = wg4[k4], bbv = wb4[k4];
        dacc += cv.x*a.x   + cv.y*a.y   + cv.z*a.z   + cv.w*a.w;
        gacc += cv.x*bgv.x + cv.y*bgv.y + cv.z*bgv.z + cv.w*bgv.w;
        bacc += cv.x*bbv.x + cv.y*bbv.y + cv.z*bbv.z + cv.w*bbv.w;
    }
    const float mval = M[(size_t)(row0 + r)*16 + j];
    const float G  = (1.0f / (1.0f + __expf(-gacc))) * ssens[j];
    const float Bt = tanhf(bacc);
    const float mu = mval * (1.0f - G) + dacc * G + 0.1f * Bt;

    float sum = mu;
#pragma unroll
    for (int off = 8; off; off >>= 1) sum += __shfl_xor_sync(0xffffffffu, sum, off, 16);
    const float mean = sum * 0.0625f;
    const float d = mu - mean;
    float v = d * d;
#pragma unroll
    for (int off = 8; off; off >>= 1) v += __shfl_xor_sync(0xffffffffu, v, off, 16);
    const float var = v * 0.0625f;
    out[(size_t)(row0 + r)*16 + j] = d * rsqrtf(var + 1e-6f) * sgam[j] + sbet[j];
}

// ---------------------------------------------------------------------------
extern "C" void kernel_launch(void* const* d_in, const int* in_sizes, int n_in,
                              void* d_out, int out_size)
{
    const float* M  = (const float*)d_in[0];
    const float* Wq = (const float*)d_in[1];  const float* bq = (const float*)d_in[2];
    const float* Wk = (const float*)d_in[3];  const float* bk = (const float*)d_in[4];
    const float* Wv = (const float*)d_in[5];  const float* bv = (const float*)d_in[6];
    const float* Wo = (const float*)d_in[7];  const float* bo = (const float*)d_in[8];
    const float* Wg = (const float*)d_in[9];  const float* bg = (const float*)d_in[10];
    const float* Wb = (const float*)d_in[11]; const float* bb = (const float*)d_in[12];
    const float* gamma = (const float*)d_in[13];
    const float* beta  = (const float*)d_in[14];
    const float* sens  = (const float*)d_in[15];
    float* out = (float*)d_out;

    qkv_kernel<<<NROW/16, 128>>>(M, Wq, bq, Wk, bk, Wv, bv);
    attn_kernel<<<dim3(TT/128, NH, BB), 128>>>();
    epi_kernel<<<NROW/16, 256>>>(M, Wo, bo, Wg, bg, Wb, bb, gamma, beta, sens, out);
}